// round 14
// baseline (speedup 1.0000x reference)
#include <cuda_runtime.h>

// AdaptivePooling2D: [16,225,225,256] f32 -> [16,7,7,256] f32 (channels_last)
// Windows: [32*o, 32*o+33) in both dims, weight 1/1089 combined.
//
// Round-14 = round-13 optimum (121.3us, 7.00 TB/s, regs 37, block 256) with
// one index-order change: grp is now the FASTEST work dim after c4, so each
// 256-thread block covers 4 adjacent 8-col groups = 32 contiguous w-columns
// in ONE row band -> 16KB contiguous block footprint per row-step (r1-pass1's
// layout, the only config ever to hit 7.07 TB/s). r13's ox-fastest order gave
// each block 4 scattered row bands. Body/regs/atomics unchanged.
//
// Design: thread = (b, ox, grp, c4) sums an 8-column x 33-row sub-window in
// registers (compile-time loop, unroll 2), one 4-float atomic scatter + one
// for the shared boundary column w=32k. ~0.87M scalar atomics, 851 MB traffic.

#define BB 16
#define HH 225
#define WW 225
#define C4 64            // 256 channels / 4 (float4)
#define OX 7
#define OY 7
#define NGRP 29          // 28 groups of 8 cols (w 0..223) + 1 group {224}

__global__ void __launch_bounds__(256)
pool_grouped_gfast_kernel(const float4* __restrict__ in, float* __restrict__ out)
{
    const int N = BB * C4 * NGRP * OX;     // 207,872 threads
    int idx = blockIdx.x * blockDim.x + threadIdx.x;
    if (idx >= N) return;

    const int c4 = idx & (C4 - 1);
    int t = idx >> 6;
    const int grp = t % NGRP;              // FASTEST work dim: adjacent blocks
    t /= NGRP;                             // cover adjacent column groups
    const int ox  = t % OX;
    const int b   = t / OX;

    const int w0 = grp * 8;
    const int h0 = ox * 32;

    // Primary output column window; cap w=224 (k=7) into window 6.
    const int k   = grp >> 2;
    const int oyP = (k < OY) ? k : (OY - 1);
    // First column of this group is a shared boundary column (w = 32k,
    // 1 <= k <= 6): its column-sum also feeds window k-1.
    const bool dual = ((grp & 3) == 0) && (grp >= 4) && (grp <= 24);
    const int oyD = k - 1;

    const float4* __restrict__ p =
        in + ((size_t)(b * HH + h0) * WW + w0) * C4 + c4;
    const size_t rs = (size_t)WW * C4;     // row stride in float4 units

    float4 acc  = make_float4(0.f, 0.f, 0.f, 0.f);  // all columns in group
    float4 acc0 = make_float4(0.f, 0.f, 0.f, 0.f);  // column j=0 only

    if (grp == NGRP - 1) {
        // Last group: single column w=224.
#pragma unroll 3
        for (int i = 0; i < 33; ++i) {
            float4 v = __ldg(p);
            p += rs;
            acc.x += v.x; acc.y += v.y; acc.z += v.z; acc.w += v.w;
        }
    } else {
#pragma unroll 2
        for (int i = 0; i < 33; ++i) {
            float4 v0 = __ldg(p + 0 * C4);
            float4 v1 = __ldg(p + 1 * C4);
            float4 v2 = __ldg(p + 2 * C4);
            float4 v3 = __ldg(p + 3 * C4);
            float4 v4 = __ldg(p + 4 * C4);
            float4 v5 = __ldg(p + 5 * C4);
            float4 v6 = __ldg(p + 6 * C4);
            float4 v7 = __ldg(p + 7 * C4);
            p += rs;

            acc0.x += v0.x; acc0.y += v0.y; acc0.z += v0.z; acc0.w += v0.w;

            float sx = v0.x + v1.x + v2.x + v3.x + v4.x + v5.x + v6.x + v7.x;
            float sy = v0.y + v1.y + v2.y + v3.y + v4.y + v5.y + v6.y + v7.y;
            float sz = v0.z + v1.z + v2.z + v3.z + v4.z + v5.z + v6.z + v7.z;
            float sw = v0.w + v1.w + v2.w + v3.w + v4.w + v5.w + v6.w + v7.w;
            acc.x += sx; acc.y += sy; acc.z += sz; acc.w += sw;
        }
    }

    const float s = 1.0f / (33.0f * 33.0f);

    float* o0 = out + ((((size_t)(b * OX + ox) * OY + oyP) * C4 + c4) << 2);
    atomicAdd(o0 + 0, acc.x * s);
    atomicAdd(o0 + 1, acc.y * s);
    atomicAdd(o0 + 2, acc.z * s);
    atomicAdd(o0 + 3, acc.w * s);

    if (dual) {
        float* o1 = out + ((((size_t)(b * OX + ox) * OY + oyD) * C4 + c4) << 2);
        atomicAdd(o1 + 0, acc0.x * s);
        atomicAdd(o1 + 1, acc0.y * s);
        atomicAdd(o1 + 2, acc0.z * s);
        atomicAdd(o1 + 3, acc0.w * s);
    }
}

extern "C" void kernel_launch(void* const* d_in, const int* in_sizes, int n_in,
                              void* d_out, int out_size)
{
    (void)in_sizes; (void)n_in;
    const float4* in = (const float4*)d_in[0];
    float* out = (float*)d_out;

    // Output is poisoned (0xAA) by the harness; atomics need zeros.
    cudaMemsetAsync(d_out, 0, (size_t)out_size * sizeof(float));

    const int n = BB * C4 * NGRP * OX;     // 207,872
    pool_grouped_gfast_kernel<<<(n + 255) / 256, 256>>>(in, out);
}

// round 15
// speedup vs baseline: 1.0113x; 1.0113x over previous
#include <cuda_runtime.h>

// AdaptivePooling2D: [16,225,225,256] f32 -> [16,7,7,256] f32 (channels_last)
// Windows: [32*o, 32*o+33) in both dims, weight 1/1089 combined.
//
// FINAL = round-13, the measured optimum across a 14-round sweep:
//   121.3us, 7.00 TB/s (87.5% of 8TB/s spec), regs 37, rel_err 1.76e-7.
// Swept and rejected: scratch two-pass (133), per-column atomics (128-130),
// 4-col groups (127), row-split variants (133-152: reg bloat), zero-redundancy
// peeling (129-152: reg bloat + stream disruption), unroll 3 (141), __ldcs
// (152), grp-fastest order (123). The 8-col/unroll-2/37-reg/256-block shape
// with ox-fastest ordering is the unique rate optimum; remaining headroom to
// the demonstrated pattern ceiling (7.07 TB/s) is ~1us.
//
// Design: thread = (b, c4, grp, ox) sums an 8-column x 33-row sub-window in
// registers (4KB contiguous per warp per row-step, compile-time loop,
// unroll 2), then ONE 4-float atomic scatter into out[b,ox,oy(grp)], plus one
// more for the shared boundary column w=32k (accumulated separately in acc0).
// ~0.87M scalar atomics; 851 MB traffic (only boundary rows/cols read twice).

#define BB 16
#define HH 225
#define WW 225
#define C4 64            // 256 channels / 4 (float4)
#define OX 7
#define OY 7
#define NGRP 29          // 28 groups of 8 cols (w 0..223) + 1 group {224}

__global__ void __launch_bounds__(256)
pool_grouped_b256_kernel(const float4* __restrict__ in, float* __restrict__ out)
{
    const int N = BB * C4 * NGRP * OX;     // 207,872 threads
    int idx = blockIdx.x * blockDim.x + threadIdx.x;
    if (idx >= N) return;

    const int c4 = idx & (C4 - 1);
    int t = idx >> 6;
    const int ox  = t % OX;
    t /= OX;
    const int grp = t % NGRP;
    const int b   = t / NGRP;

    const int w0 = grp * 8;
    const int h0 = ox * 32;

    // Primary output column window; cap w=224 (k=7) into window 6.
    const int k   = grp >> 2;
    const int oyP = (k < OY) ? k : (OY - 1);
    // First column of this group is a shared boundary column (w = 32k,
    // 1 <= k <= 6): its column-sum also feeds window k-1.
    const bool dual = ((grp & 3) == 0) && (grp >= 4) && (grp <= 24);
    const int oyD = k - 1;

    const float4* __restrict__ p =
        in + ((size_t)(b * HH + h0) * WW + w0) * C4 + c4;
    const size_t rs = (size_t)WW * C4;     // row stride in float4 units

    float4 acc  = make_float4(0.f, 0.f, 0.f, 0.f);  // all columns in group
    float4 acc0 = make_float4(0.f, 0.f, 0.f, 0.f);  // column j=0 only

    if (grp == NGRP - 1) {
        // Last group: single column w=224.
#pragma unroll 3
        for (int i = 0; i < 33; ++i) {
            float4 v = __ldg(p);
            p += rs;
            acc.x += v.x; acc.y += v.y; acc.z += v.z; acc.w += v.w;
        }
    } else {
#pragma unroll 2
        for (int i = 0; i < 33; ++i) {
            float4 v0 = __ldg(p + 0 * C4);
            float4 v1 = __ldg(p + 1 * C4);
            float4 v2 = __ldg(p + 2 * C4);
            float4 v3 = __ldg(p + 3 * C4);
            float4 v4 = __ldg(p + 4 * C4);
            float4 v5 = __ldg(p + 5 * C4);
            float4 v6 = __ldg(p + 6 * C4);
            float4 v7 = __ldg(p + 7 * C4);
            p += rs;

            acc0.x += v0.x; acc0.y += v0.y; acc0.z += v0.z; acc0.w += v0.w;

            float sx = v0.x + v1.x + v2.x + v3.x + v4.x + v5.x + v6.x + v7.x;
            float sy = v0.y + v1.y + v2.y + v3.y + v4.y + v5.y + v6.y + v7.y;
            float sz = v0.z + v1.z + v2.z + v3.z + v4.z + v5.z + v6.z + v7.z;
            float sw = v0.w + v1.w + v2.w + v3.w + v4.w + v5.w + v6.w + v7.w;
            acc.x += sx; acc.y += sy; acc.z += sz; acc.w += sw;
        }
    }

    const float s = 1.0f / (33.0f * 33.0f);

    float* o0 = out + ((((size_t)(b * OX + ox) * OY + oyP) * C4 + c4) << 2);
    atomicAdd(o0 + 0, acc.x * s);
    atomicAdd(o0 + 1, acc.y * s);
    atomicAdd(o0 + 2, acc.z * s);
    atomicAdd(o0 + 3, acc.w * s);

    if (dual) {
        float* o1 = out + ((((size_t)(b * OX + ox) * OY + oyD) * C4 + c4) << 2);
        atomicAdd(o1 + 0, acc0.x * s);
        atomicAdd(o1 + 1, acc0.y * s);
        atomicAdd(o1 + 2, acc0.z * s);
        atomicAdd(o1 + 3, acc0.w * s);
    }
}

extern "C" void kernel_launch(void* const* d_in, const int* in_sizes, int n_in,
                              void* d_out, int out_size)
{
    (void)in_sizes; (void)n_in;
    const float4* in = (const float4*)d_in[0];
    float* out = (float*)d_out;

    // Output is poisoned (0xAA) by the harness; atomics need zeros.
    cudaMemsetAsync(d_out, 0, (size_t)out_size * sizeof(float));

    const int n = BB * C4 * NGRP * OX;     // 207,872
    pool_grouped_b256_kernel<<<(n + 255) / 256, 256>>>(in, out);
}

// round 16
// speedup vs baseline: 1.0135x; 1.0021x over previous
#include <cuda_runtime.h>

// AdaptivePooling2D: [16,225,225,256] f32 -> [16,7,7,256] f32 (channels_last)
// Windows: [32*o, 32*o+33) in both dims, weight 1/1089 combined.
//
// Round-16 = round-13 optimum (121.3us, 7.00 TB/s, regs 37) with the last
// unswept residency point: block 192. At 37 regs, 192-thread CTAs pack
// 9/SM = 1728 resident threads (vs 1536 @256, 1408 @128) — the r4->r13 data
// (1408->1536, +0.05 TB/s) says resident stream count still has marginal
// value. Body/mapping/regs identical; bounded downside.
//
// Design: thread = (b, c4, grp, ox) sums an 8-column x 33-row sub-window in
// registers (4KB contiguous per warp per row-step, compile-time loop,
// unroll 2), then ONE 4-float atomic scatter + one for the shared boundary
// column w=32k. ~0.87M scalar atomics; 851 MB traffic.

#define BB 16
#define HH 225
#define WW 225
#define C4 64            // 256 channels / 4 (float4)
#define OX 7
#define OY 7
#define NGRP 29          // 28 groups of 8 cols (w 0..223) + 1 group {224}

__global__ void __launch_bounds__(192)
pool_grouped_b192_kernel(const float4* __restrict__ in, float* __restrict__ out)
{
    const int N = BB * C4 * NGRP * OX;     // 207,872 threads
    int idx = blockIdx.x * blockDim.x + threadIdx.x;
    if (idx >= N) return;

    const int c4 = idx & (C4 - 1);
    int t = idx >> 6;
    const int ox  = t % OX;
    t /= OX;
    const int grp = t % NGRP;
    const int b   = t / NGRP;

    const int w0 = grp * 8;
    const int h0 = ox * 32;

    // Primary output column window; cap w=224 (k=7) into window 6.
    const int k   = grp >> 2;
    const int oyP = (k < OY) ? k : (OY - 1);
    // First column of this group is a shared boundary column (w = 32k,
    // 1 <= k <= 6): its column-sum also feeds window k-1.
    const bool dual = ((grp & 3) == 0) && (grp >= 4) && (grp <= 24);
    const int oyD = k - 1;

    const float4* __restrict__ p =
        in + ((size_t)(b * HH + h0) * WW + w0) * C4 + c4;
    const size_t rs = (size_t)WW * C4;     // row stride in float4 units

    float4 acc  = make_float4(0.f, 0.f, 0.f, 0.f);  // all columns in group
    float4 acc0 = make_float4(0.f, 0.f, 0.f, 0.f);  // column j=0 only

    if (grp == NGRP - 1) {
        // Last group: single column w=224.
#pragma unroll 3
        for (int i = 0; i < 33; ++i) {
            float4 v = __ldg(p);
            p += rs;
            acc.x += v.x; acc.y += v.y; acc.z += v.z; acc.w += v.w;
        }
    } else {
#pragma unroll 2
        for (int i = 0; i < 33; ++i) {
            float4 v0 = __ldg(p + 0 * C4);
            float4 v1 = __ldg(p + 1 * C4);
            float4 v2 = __ldg(p + 2 * C4);
            float4 v3 = __ldg(p + 3 * C4);
            float4 v4 = __ldg(p + 4 * C4);
            float4 v5 = __ldg(p + 5 * C4);
            float4 v6 = __ldg(p + 6 * C4);
            float4 v7 = __ldg(p + 7 * C4);
            p += rs;

            acc0.x += v0.x; acc0.y += v0.y; acc0.z += v0.z; acc0.w += v0.w;

            float sx = v0.x + v1.x + v2.x + v3.x + v4.x + v5.x + v6.x + v7.x;
            float sy = v0.y + v1.y + v2.y + v3.y + v4.y + v5.y + v6.y + v7.y;
            float sz = v0.z + v1.z + v2.z + v3.z + v4.z + v5.z + v6.z + v7.z;
            float sw = v0.w + v1.w + v2.w + v3.w + v4.w + v5.w + v6.w + v7.w;
            acc.x += sx; acc.y += sy; acc.z += sz; acc.w += sw;
        }
    }

    const float s = 1.0f / (33.0f * 33.0f);

    float* o0 = out + ((((size_t)(b * OX + ox) * OY + oyP) * C4 + c4) << 2);
    atomicAdd(o0 + 0, acc.x * s);
    atomicAdd(o0 + 1, acc.y * s);
    atomicAdd(o0 + 2, acc.z * s);
    atomicAdd(o0 + 3, acc.w * s);

    if (dual) {
        float* o1 = out + ((((size_t)(b * OX + ox) * OY + oyD) * C4 + c4) << 2);
        atomicAdd(o1 + 0, acc0.x * s);
        atomicAdd(o1 + 1, acc0.y * s);
        atomicAdd(o1 + 2, acc0.z * s);
        atomicAdd(o1 + 3, acc0.w * s);
    }
}

extern "C" void kernel_launch(void* const* d_in, const int* in_sizes, int n_in,
                              void* d_out, int out_size)
{
    (void)in_sizes; (void)n_in;
    const float4* in = (const float4*)d_in[0];
    float* out = (float*)d_out;

    // Output is poisoned (0xAA) by the harness; atomics need zeros.
    cudaMemsetAsync(d_out, 0, (size_t)out_size * sizeof(float));

    const int n = BB * C4 * NGRP * OX;     // 207,872
    pool_grouped_b192_kernel<<<(n + 191) / 192, 192>>>(in, out);
}